// round 5
// baseline (speedup 1.0000x reference)
#include <cuda_runtime.h>
#include <cuda_bf16.h>
#include <cstdint>

// Output = one_hot(arange(N), N) @ W = I @ W = W: an 8 MiB D2D copy.
//
// R1-R4: four different copy paths (LDG grid-stride, CE memcpy, LDG MLP4,
// TMA bulk) ALL land at 6.4-6.9us with every counter idle -> a shared,
// implementation-independent floor, consistent with the LTS cap at an
// un-ramped (idle DVFS) clock (~2.7 TB/s).
//
// R5: split the copy across the TWO independent engines concurrently:
//   - SM kernel (MLP4 LDG.128/STG.128) copies the lower 4 MiB on the
//     capture stream,
//   - copy engine (cudaMemcpyAsync D2D) copies the upper 4 MiB on a
//     second stream, forked/joined with events (graph-capturable).
// If their throughput limiters are independent, ~2x -> ~4us.

__global__ void __launch_bounds__(256) copy_w_mlp4(const float4* __restrict__ src,
                                                   float4* __restrict__ dst) {
    int base = blockIdx.x * (256 * 4) + threadIdx.x;
    float4 a0 = src[base + 0 * 256];
    float4 a1 = src[base + 1 * 256];
    float4 a2 = src[base + 2 * 256];
    float4 a3 = src[base + 3 * 256];
    dst[base + 0 * 256] = a0;
    dst[base + 1 * 256] = a1;
    dst[base + 2 * 256] = a2;
    dst[base + 3 * 256] = a3;
}

namespace {
struct ForkResources {
    cudaStream_t s2;
    cudaEvent_t ev_fork;
    cudaEvent_t ev_join;
    ForkResources() {
        cudaStreamCreateWithFlags(&s2, cudaStreamNonBlocking);
        cudaEventCreateWithFlags(&ev_fork, cudaEventDisableTiming);
        cudaEventCreateWithFlags(&ev_join, cudaEventDisableTiming);
    }
};
ForkResources& res() {
    static ForkResources r;  // host-side objects only; no device memory
    return r;
}
}  // namespace

extern "C" void kernel_launch(void* const* d_in, const int* in_sizes, int n_in,
                              void* d_out, int out_size) {
    const char* W = (const char*)d_in[0];
    char* out = (char*)d_out;
    size_t total_bytes = (size_t)out_size * sizeof(float);  // 8 MiB
    size_t half = total_bytes / 2;                          // 4 MiB each

    ForkResources& r = res();

    // Fork: second stream depends on everything prior on the capture stream.
    cudaEventRecord(r.ev_fork, 0);
    cudaStreamWaitEvent(r.s2, r.ev_fork, 0);

    // Branch A (SM): lower half via MLP4 kernel on stream 0.
    // half/16 bytes per vec4 = 262144 vec4; /(256*4) = 256 CTAs, exact.
    int blocks = (int)(half / (16 * 256 * 4));
    copy_w_mlp4<<<blocks, 256, 0, 0>>>((const float4*)W, (float4*)out);

    // Branch B (CE): upper half via copy engine on stream s2.
    cudaMemcpyAsync(out + half, W + half, half, cudaMemcpyDeviceToDevice, r.s2);

    // Join: capture stream waits for the CE branch.
    cudaEventRecord(r.ev_join, r.s2);
    cudaStreamWaitEvent(0, r.ev_join, 0);
}

// round 6
// speedup vs baseline: 1.0417x; 1.0417x over previous
#include <cuda_runtime.h>
#include <cuda_bf16.h>
#include <cstdint>

// Output = one_hot(arange(N), N) @ W = I @ W = W: an 8 MiB D2D copy.
//
// Established across R1-R5: every copy path (LDG, CE memcpy, TMA bulk,
// SM+CE split) lands at 6.4-7.2us because the binding constraint is the
// chip-wide LTS (L2) throughput cap (~6300 B/cyc) evaluated at the idle
// DVFS clock (~450 MHz): 16 MiB mandatory L2 traffic (8 read + 8 write)
// / 2.85 TB/s = 5.9us, which R3's kernel hit exactly. This round keeps
// the optimal single-node shape and removes the one remaining non-LTS
// cost: L1 allocation on the loads (__ldcg -> L2-only, stream-once).

__global__ void __launch_bounds__(256) copy_w_cg(const float4* __restrict__ src,
                                                 float4* __restrict__ dst) {
    // 512 CTAs x 256 threads x 4 vec4 = 524288 vec4 = 8 MiB, exact tiling.
    // Loads front-batched (MLP_p1 = 4), fully coalesced 128B per warp-access.
    int base = blockIdx.x * (256 * 4) + threadIdx.x;

    float4 a0 = __ldcg(&src[base + 0 * 256]);
    float4 a1 = __ldcg(&src[base + 1 * 256]);
    float4 a2 = __ldcg(&src[base + 2 * 256]);
    float4 a3 = __ldcg(&src[base + 3 * 256]);

    dst[base + 0 * 256] = a0;
    dst[base + 1 * 256] = a1;
    dst[base + 2 * 256] = a2;
    dst[base + 3 * 256] = a3;
}

extern "C" void kernel_launch(void* const* d_in, const int* in_sizes, int n_in,
                              void* d_out, int out_size) {
    const float4* W = (const float4*)d_in[0];
    float4* out = (float4*)d_out;
    // out_size = 16384*128 = 2097152 floats = 524288 vec4 -> 512 CTAs exact.
    int blocks = out_size / (4 * 256 * 4);
    copy_w_cg<<<blocks, 256>>>(W, out);
}

// round 7
// speedup vs baseline: 1.0817x; 1.0385x over previous
#include <cuda_runtime.h>
#include <cuda_bf16.h>
#include <cstdint>

// Output = one_hot(arange(N), N) @ W = I @ W = W: an 8 MiB D2D copy.
//
// Model established over R1-R6: T ~= 4.1us fixed + ~1.8us per 8MiB.
// The fixed term is the serial chain (graph replay + launch + one memory
// round-trip + drain) at the un-ramped idle DVFS clock; it is invariant
// to request path (LDG/TMA/CE), occupancy (2.6%..80%), and cache ops.
// Traffic (8 MiB read + 8 MiB write) is the information-theoretic
// minimum. Final shape: single kernel node, 256 CTAs x 256 threads x
// 8 vec4, all 8 independent 16B loads front-batched (one overlapped
// memory latency per thread, zero loops/branches/bounds checks).

__global__ void __launch_bounds__(256) copy_w_mlp8(const float4* __restrict__ src,
                                                   float4* __restrict__ dst) {
    // 256 CTAs x 256 threads x 8 vec4 = 524288 vec4 = 8 MiB, exact.
    // Each CTA owns a contiguous 32 KiB tile; stride-256 within the tile
    // keeps every warp access a fully coalesced 128B line.
    int base = blockIdx.x * (256 * 8) + threadIdx.x;

    float4 a0 = src[base + 0 * 256];
    float4 a1 = src[base + 1 * 256];
    float4 a2 = src[base + 2 * 256];
    float4 a3 = src[base + 3 * 256];
    float4 a4 = src[base + 4 * 256];
    float4 a5 = src[base + 5 * 256];
    float4 a6 = src[base + 6 * 256];
    float4 a7 = src[base + 7 * 256];

    dst[base + 0 * 256] = a0;
    dst[base + 1 * 256] = a1;
    dst[base + 2 * 256] = a2;
    dst[base + 3 * 256] = a3;
    dst[base + 4 * 256] = a4;
    dst[base + 5 * 256] = a5;
    dst[base + 6 * 256] = a6;
    dst[base + 7 * 256] = a7;
}

extern "C" void kernel_launch(void* const* d_in, const int* in_sizes, int n_in,
                              void* d_out, int out_size) {
    const float4* W = (const float4*)d_in[0];
    float4* out = (float4*)d_out;
    // out_size = 16384*128 = 2097152 floats = 524288 vec4 -> 256 CTAs exact.
    int blocks = out_size / (4 * 256 * 8);
    copy_w_mlp8<<<blocks, 256>>>(W, out);
}